// round 14
// baseline (speedup 1.0000x reference)
#include <cuda_runtime.h>
#include <cstdint>
#include <math.h>

typedef unsigned long long u64;

#define NLAYER 2
#define Bsz    32
#define Tsz    128
#define IN     512
#define HID    512
#define CELLN  4096
#define GATES  16384   /* 4*CELL */

// ---------------- scratch (device globals; no allocation allowed) ----------
__device__ float g_P[(size_t)2*4096*16384]; // [dir][row=b*T+t][16384]
__device__ float g_h[2*Bsz*HID];            // [dir][b][512]
__device__ float g_c[2*Bsz*CELLN];          // [dir][b][4096]
__device__ float g_pv[2*Bsz*CELLN];         // o*tanh(c_new), per step
__device__ float g_hpart[8*2*Bsz*HID];      // [ksplit=8][dir][b][512]

// ---------------- f32x2 helpers (FFMA2 path, sm_103a) ----------------------
__device__ __forceinline__ u64 dup2(float v) {
    u64 r; asm("mov.b64 %0, {%1, %1};" : "=l"(r) : "f"(v)); return r;
}
__device__ __forceinline__ void fma2(u64 &acc, u64 a, u64 b) {
    asm("fma.rn.f32x2 %0, %1, %2, %0;" : "+l"(acc) : "l"(a), "l"(b));
}
__device__ __forceinline__ float2 unpk(u64 v) {
    float2 f; asm("mov.b64 {%0, %1}, %2;" : "=f"(f.x), "=f"(f.y) : "l"(v)); return f;
}
__device__ __forceinline__ float sigmoidf_(float x) { return 1.0f / (1.0f + expf(-x)); }

// ============================================================================
// Kernel A: P = X . Wx^T + b.  M=4096 rows(b*T+t), N=16384, K=512.
// Tile 128x128x32, 256 threads, 8x8 outputs/thread (4 row-pairs x 8 cols).
// (unchanged from R12 — near its FFMA2 floor; tcgen05 is the next-round fix)
// ============================================================================
__global__ void __launch_bounds__(256)
k_wx(const float* __restrict__ x0, const float* __restrict__ x1, int xstride,
     const float* __restrict__ Wx, const float* __restrict__ bias, int layer)
{
    const int dir = blockIdx.z;
    const float* __restrict__ X  = dir ? x1 : x0;
    const float* __restrict__ W  = Wx   + (size_t)(layer*2 + dir) * GATES * IN;
    const float* __restrict__ bb = bias + (size_t)(layer*2 + dir) * GATES;
    float* __restrict__ Pd = g_P + (size_t)dir * 4096 * GATES;

    __shared__ __align__(16) float As[32][132];
    __shared__ __align__(16) float Bs[32][132];

    const int tid = threadIdx.x;
    const int tx  = tid & 15;
    const int ty  = tid >> 4;
    const int row0 = blockIdx.x * 128;
    const int col0 = blockIdx.y * 128;
    const int lk = tid & 31, lr = tid >> 5;

    u64 acc[4][8];
#pragma unroll
    for (int p = 0; p < 4; p++)
#pragma unroll
        for (int j = 0; j < 8; j++) acc[p][j] = 0ull;

    for (int kc = 0; kc < IN; kc += 32) {
#pragma unroll
        for (int i = 0; i < 16; i++) {
            int r = lr + i * 8;
            As[lk][r] = X[(size_t)(row0 + r) * xstride + kc + lk];
            Bs[lk][r] = W[(size_t)(col0 + r) * IN + kc + lk];
        }
        __syncthreads();
#pragma unroll
        for (int kk = 0; kk < 32; kk++) {
            u64 a2[4];
#pragma unroll
            for (int p = 0; p < 4; p++)
                a2[p] = *(const u64*)&As[kk][ty * 8 + 2 * p];
            float4 w0 = *(const float4*)&Bs[kk][tx * 8];
            float4 w1 = *(const float4*)&Bs[kk][tx * 8 + 4];
            float wv[8] = {w0.x, w0.y, w0.z, w0.w, w1.x, w1.y, w1.z, w1.w};
#pragma unroll
            for (int j = 0; j < 8; j++) {
                u64 bd = dup2(wv[j]);
#pragma unroll
                for (int p = 0; p < 4; p++) fma2(acc[p][j], a2[p], bd);
            }
        }
        __syncthreads();
    }

    float bj[8];
#pragma unroll
    for (int j = 0; j < 8; j++) bj[j] = bb[col0 + tx * 8 + j];
#pragma unroll
    for (int p = 0; p < 4; p++) {
        size_t r0 = (size_t)(row0 + ty * 8 + 2 * p) * GATES + col0 + tx * 8;
#pragma unroll
        for (int j = 0; j < 8; j++) {
            float2 v = unpk(acc[p][j]);
            Pd[r0 + j]         = v.x + bj[j];
            Pd[r0 + GATES + j] = v.y + bj[j];
        }
    }
}

// ============================================================================
// Kernel B (REWRITTEN): one recurrent step.
// Grid (128 cell-tiles of 32 cells, 2 dirs) = 256 blocks, 128 threads.
// Block tile: 32 batch x 128 local gate cols (= 4 gates x 32 cells).
// Thread tile: 8 batch (4 f32x2 pairs) x 4 cols. 59% FFMA2 density.
// ============================================================================
__global__ void __launch_bounds__(128)
k_gates(const float* __restrict__ Wh, const int* __restrict__ mask, int layer, int s)
{
    const int dir = blockIdx.y;
    const int t   = dir ? (Tsz - 1 - s) : s;
    const int c0  = blockIdx.x * 32;
    const float* __restrict__ W  = Wh + (size_t)(layer*2 + dir) * GATES * HID;
    const float* __restrict__ Pd = g_P + (size_t)dir * 4096 * GATES;
    const float* __restrict__ h  = g_h + dir * Bsz * HID;
    float* __restrict__ c  = g_c  + dir * Bsz * CELLN;
    float* __restrict__ pv = g_pv + dir * Bsz * CELLN;

    __shared__ __align__(16) float hs[32 * 36];   // [k][b], pad 36 (16B-aligned reads)
    __shared__ __align__(16) float ws[32 * 132];  // [k][lc], pad 132; aliased as Gs
    float* Gs = ws;                                // [b][132] gate values after GEMM

    const int tid = threadIdx.x;
    const int tx  = tid & 31;      // local col base tx*4 (0..127)
    const int ty  = tid >> 5;      // batch base ty*8 (0..3)

    // W row index for this thread's fill column
    const int fcol  = tid;                                   // 0..127
    const int fgrow = (fcol >> 5) * CELLN + c0 + (fcol & 31);
    const int flk   = tid & 31, fbq = tid >> 5;

    u64 acc[4][4];   // [bpair][ncol]
#pragma unroll
    for (int p = 0; p < 4; p++)
#pragma unroll
        for (int j = 0; j < 4; j++) acc[p][j] = 0ull;

    for (int kc = 0; kc < HID; kc += 32) {
        // fill hs[k][b]: coalesced LDG over k
#pragma unroll
        for (int i = 0; i < 8; i++) {
            int b = fbq * 8 + i;
            hs[flk * 36 + b] = h[b * HID + kc + flk];
        }
        // fill ws[k][lc]: each thread owns one gate col, 32 consecutive k
        const float* wr = W + (size_t)fgrow * HID + kc;
#pragma unroll
        for (int q = 0; q < 8; q++) {
            float4 w4 = *(const float4*)(wr + q * 4);
            ws[(q * 4 + 0) * 132 + fcol] = w4.x;
            ws[(q * 4 + 1) * 132 + fcol] = w4.y;
            ws[(q * 4 + 2) * 132 + fcol] = w4.z;
            ws[(q * 4 + 3) * 132 + fcol] = w4.w;
        }
        __syncthreads();
#pragma unroll
        for (int kk = 0; kk < 32; kk++) {
            float4 ha = *(const float4*)&hs[kk * 36 + ty * 8];
            float4 hb = *(const float4*)&hs[kk * 36 + ty * 8 + 4];
            u64 h2[4];
            h2[0] = *(const u64*)&ha.x;  h2[1] = *(const u64*)&ha.z;
            h2[2] = *(const u64*)&hb.x;  h2[3] = *(const u64*)&hb.z;
            float4 wv = *(const float4*)&ws[kk * 132 + tx * 4];
            float wa[4] = {wv.x, wv.y, wv.z, wv.w};
#pragma unroll
            for (int j = 0; j < 4; j++) {
                u64 wd = dup2(wa[j]);
#pragma unroll
                for (int p = 0; p < 4; p++) fma2(acc[p][j], h2[p], wd);
            }
        }
        __syncthreads();
    }

    // stage g = acc + P[t] into Gs[b][lc] (ws is free after last sync)
    const int gate  = tx >> 3;
    const int cell0 = (tx & 7) * 4;
#pragma unroll
    for (int p = 0; p < 4; p++) {
        int b = ty * 8 + 2 * p;
        const float* P0 = Pd + ((size_t)(b * Tsz + t) * GATES) + gate * CELLN + c0 + cell0;
        const float* P1 = P0 + (size_t)Tsz * GATES;
        float4 pl0 = *(const float4*)P0;
        float4 pl1 = *(const float4*)P1;
        float2 v0 = unpk(acc[p][0]), v1 = unpk(acc[p][1]);
        float2 v2 = unpk(acc[p][2]), v3 = unpk(acc[p][3]);
        float4 g0 = {v0.x + pl0.x, v1.x + pl0.y, v2.x + pl0.z, v3.x + pl0.w};
        float4 g1 = {v0.y + pl1.x, v1.y + pl1.y, v2.y + pl1.z, v3.y + pl1.w};
        *(float4*)&Gs[b * 132 + tx * 4]       = g0;
        *(float4*)&Gs[(b + 1) * 132 + tx * 4] = g1;
    }
    __syncthreads();

    // elementwise cell update: 1024 (b,cell) pairs / 128 threads
#pragma unroll
    for (int i = 0; i < 8; i++) {
        int e = tid + 128 * i;
        int b = e >> 5, cell = e & 31;
        float ig = sigmoidf_(Gs[b * 132 +  0 + cell]);
        float fg = sigmoidf_(Gs[b * 132 + 32 + cell]);
        float mm =           Gs[b * 132 + 64 + cell];
        float og = sigmoidf_(Gs[b * 132 + 96 + cell]);
        int ci = b * CELLN + c0 + cell;
        float cold = c[ci];
        float cn = ig * tanhf(mm) + fg * cold;
        cn = fminf(3.0f, fmaxf(-3.0f, cn));
        float p2 = og * tanhf(cn);
        c[ci]  = mask[b * Tsz + t] ? cn : cold;
        pv[ci] = p2;
    }
}

// ============================================================================
// Kernel C (REWRITTEN): projection partials.
// Grid (8 n-tiles of 64, 8 K-splits of 512, 2 dirs) = 128 blocks x 256 thr.
// Thread tile: 4 batch (2 pairs) x 2 cols, 8 independent accumulators.
// ============================================================================
__global__ void __launch_bounds__(256)
k_proj(const float* __restrict__ Wp, int layer)
{
    const int dir = blockIdx.z;
    const int n0  = blockIdx.x * 64;
    const int k0  = blockIdx.y * 512;
    const float* __restrict__ W = Wp + (size_t)(layer*2 + dir) * HID * CELLN;
    const float* __restrict__ p = g_pv + dir * Bsz * CELLN;
    float* __restrict__ hp = g_hpart + ((size_t)blockIdx.y * 2 + dir) * Bsz * HID;

    __shared__ __align__(16) float ps[32 * 36];  // [k][b]
    __shared__ __align__(16) float ws[32 * 68];  // [k][n]

    const int tid = threadIdx.x;
    const int tx  = tid & 31;      // n base tx*2 (0..63)
    const int ty  = tid >> 5;      // b base ty*4 (0..7)

    const int flk = tid & 31, fbq = tid >> 5;   // ps fill
    const int fn  = tid & 63, fkq = tid >> 6;   // ws fill

    u64 acc[2][2];
    acc[0][0] = acc[0][1] = acc[1][0] = acc[1][1] = 0ull;

    for (int kc = k0; kc < k0 + 512; kc += 32) {
#pragma unroll
        for (int i = 0; i < 4; i++) {
            int b = fbq * 4 + i;
            ps[flk * 36 + b] = p[b * CELLN + kc + flk];
        }
        const float* wr = W + (size_t)(n0 + fn) * CELLN + kc + fkq * 8;
#pragma unroll
        for (int i = 0; i < 2; i++) {
            float4 w4 = *(const float4*)(wr + i * 4);
            int kb = fkq * 8 + i * 4;
            ws[(kb + 0) * 68 + fn] = w4.x;
            ws[(kb + 1) * 68 + fn] = w4.y;
            ws[(kb + 2) * 68 + fn] = w4.z;
            ws[(kb + 3) * 68 + fn] = w4.w;
        }
        __syncthreads();
#pragma unroll
        for (int kk = 0; kk < 32; kk++) {
            u64 a0 = *(const u64*)&ps[kk * 36 + ty * 4];
            u64 a1 = *(const u64*)&ps[kk * 36 + ty * 4 + 2];
            float2 wv = *(const float2*)&ws[kk * 68 + tx * 2];
            u64 w0 = dup2(wv.x), w1 = dup2(wv.y);
            fma2(acc[0][0], a0, w0); fma2(acc[0][1], a0, w1);
            fma2(acc[1][0], a1, w0); fma2(acc[1][1], a1, w1);
        }
        __syncthreads();
    }

#pragma unroll
    for (int bp = 0; bp < 2; bp++) {
#pragma unroll
        for (int n = 0; n < 2; n++) {
            float2 v = unpk(acc[bp][n]);
            int b = ty * 4 + 2 * bp, col = n0 + tx * 2 + n;
            hp[b * HID + col]       = v.x;
            hp[(b + 1) * HID + col] = v.y;
        }
    }
}

// ============================================================================
// Kernel F: finalize — sum 8 K-split partials, clip +-3, mask, write h + out.
// ============================================================================
__global__ void __launch_bounds__(256)
k_final(const int* __restrict__ mask, int layer, int s, float* __restrict__ out)
{
    int e = blockIdx.x * 256 + threadIdx.x;   // 0..32767 = [dir][b][n]
    int dir = e >> 14;
    int b   = (e >> 9) & 31;
    int n   = e & 511;
    int t = dir ? (Tsz - 1 - s) : s;
    float hv = 0.0f;
#pragma unroll
    for (int ks = 0; ks < 8; ks++) hv += g_hpart[ks * 32768 + e];
    hv = fminf(3.0f, fmaxf(-3.0f, hv));
    int m = mask[b * Tsz + t];
    float hold = g_h[e];
    g_h[e] = m ? hv : hold;
    out[(((size_t)layer * Bsz + b) * Tsz + t) * 1024 + dir * HID + n] = m ? hv : 0.0f;
}

__global__ void __launch_bounds__(256) k_init()
{
    int i = blockIdx.x * 256 + threadIdx.x;   // grid covers 262144
    if (i < 2 * Bsz * HID)   g_h[i] = 0.0f;
    if (i < 2 * Bsz * CELLN) g_c[i] = 0.0f;
}

// residual skip: out[layer1] += out[layer0]
__global__ void __launch_bounds__(256) k_resid(float* __restrict__ out)
{
    size_t i = (size_t)blockIdx.x * 256 + threadIdx.x;  // 4,194,304 total
    out[(size_t)4194304 + i] += out[i];
}

extern "C" void kernel_launch(void* const* d_in, const int* in_sizes, int n_in,
                              void* d_out, int out_size)
{
    const float* x    = (const float*)d_in[0];
    const int*   mask = (const int*)  d_in[1];
    const float* Wx   = (const float*)d_in[2];
    const float* Wh   = (const float*)d_in[3];
    const float* bias = (const float*)d_in[4];
    const float* Wp   = (const float*)d_in[5];
    float* out = (float*)d_out;

    for (int layer = 0; layer < NLAYER; layer++) {
        k_init<<<1024, 256>>>();

        const float* x0; const float* x1; int xs;
        if (layer == 0) { x0 = x;   x1 = x;         xs = IN;   }
        else            { x0 = out; x1 = out + 512; xs = 1024; }

        dim3 gwx(4096 / 128, GATES / 128, 2);
        k_wx<<<gwx, 256>>>(x0, x1, xs, Wx, bias, layer);

        for (int s = 0; s < Tsz; s++) {
            k_gates<<<dim3(128, 2), 128>>>(Wh, mask, layer, s);
            k_proj <<<dim3(8, 8, 2), 256>>>(Wp, layer);
            k_final<<<128, 256>>>(mask, layer, s, out);
        }
    }
    k_resid<<<16384, 256>>>(out);
}

// round 15
// speedup vs baseline: 1.0043x; 1.0043x over previous
#include <cuda_runtime.h>
#include <cstdint>
#include <math.h>

typedef unsigned long long u64;

#define NLAYER 2
#define Bsz    32
#define Tsz    128
#define IN     512
#define HID    512
#define CELLN  4096
#define GATES  16384   /* 4*CELL */

// ---------------- scratch (device globals; no allocation allowed) ----------
__device__ float g_P[(size_t)2*4096*16384]; // [dir][row=b*T+t][16384]
__device__ float g_h[2*Bsz*HID];            // [dir][b][512]
__device__ float g_c[2*Bsz*CELLN];          // [dir][b][4096]
__device__ float g_pv[2*Bsz*CELLN];         // o*tanh(c_new), per step
__device__ float g_hpart[8*2*Bsz*HID];      // [ksplit=8][dir][b][512]

// ---------------- f32x2 helpers (FFMA2 path, sm_103a) ----------------------
__device__ __forceinline__ u64 dup2(float v) {
    u64 r; asm("mov.b64 %0, {%1, %1};" : "=l"(r) : "f"(v)); return r;
}
__device__ __forceinline__ void fma2(u64 &acc, u64 a, u64 b) {
    asm("fma.rn.f32x2 %0, %1, %2, %0;" : "+l"(acc) : "l"(a), "l"(b));
}
__device__ __forceinline__ float2 unpk(u64 v) {
    float2 f; asm("mov.b64 {%0, %1}, %2;" : "=f"(f.x), "=f"(f.y) : "l"(v)); return f;
}
__device__ __forceinline__ float sigmoidf_(float x) { return 1.0f / (1.0f + expf(-x)); }

// ============================================================================
// Kernel A: P = X . Wx^T + b.  M=4096 rows(b*T+t), N=16384, K=512.
// Tile 128x128x32, 256 threads, 8x8 outputs/thread (4 row-pairs x 8 cols).
// (unchanged from R12 — near its FFMA2 floor; tcgen05 is the next-round fix)
// ============================================================================
__global__ void __launch_bounds__(256)
k_wx(const float* __restrict__ x0, const float* __restrict__ x1, int xstride,
     const float* __restrict__ Wx, const float* __restrict__ bias, int layer)
{
    const int dir = blockIdx.z;
    const float* __restrict__ X  = dir ? x1 : x0;
    const float* __restrict__ W  = Wx   + (size_t)(layer*2 + dir) * GATES * IN;
    const float* __restrict__ bb = bias + (size_t)(layer*2 + dir) * GATES;
    float* __restrict__ Pd = g_P + (size_t)dir * 4096 * GATES;

    __shared__ __align__(16) float As[32][132];
    __shared__ __align__(16) float Bs[32][132];

    const int tid = threadIdx.x;
    const int tx  = tid & 15;
    const int ty  = tid >> 4;
    const int row0 = blockIdx.x * 128;
    const int col0 = blockIdx.y * 128;
    const int lk = tid & 31, lr = tid >> 5;

    u64 acc[4][8];
#pragma unroll
    for (int p = 0; p < 4; p++)
#pragma unroll
        for (int j = 0; j < 8; j++) acc[p][j] = 0ull;

    for (int kc = 0; kc < IN; kc += 32) {
#pragma unroll
        for (int i = 0; i < 16; i++) {
            int r = lr + i * 8;
            As[lk][r] = X[(size_t)(row0 + r) * xstride + kc + lk];
            Bs[lk][r] = W[(size_t)(col0 + r) * IN + kc + lk];
        }
        __syncthreads();
#pragma unroll
        for (int kk = 0; kk < 32; kk++) {
            u64 a2[4];
#pragma unroll
            for (int p = 0; p < 4; p++)
                a2[p] = *(const u64*)&As[kk][ty * 8 + 2 * p];
            float4 w0 = *(const float4*)&Bs[kk][tx * 8];
            float4 w1 = *(const float4*)&Bs[kk][tx * 8 + 4];
            float wv[8] = {w0.x, w0.y, w0.z, w0.w, w1.x, w1.y, w1.z, w1.w};
#pragma unroll
            for (int j = 0; j < 8; j++) {
                u64 bd = dup2(wv[j]);
#pragma unroll
                for (int p = 0; p < 4; p++) fma2(acc[p][j], a2[p], bd);
            }
        }
        __syncthreads();
    }

    float bj[8];
#pragma unroll
    for (int j = 0; j < 8; j++) bj[j] = bb[col0 + tx * 8 + j];
#pragma unroll
    for (int p = 0; p < 4; p++) {
        size_t r0 = (size_t)(row0 + ty * 8 + 2 * p) * GATES + col0 + tx * 8;
#pragma unroll
        for (int j = 0; j < 8; j++) {
            float2 v = unpk(acc[p][j]);
            Pd[r0 + j]         = v.x + bj[j];
            Pd[r0 + GATES + j] = v.y + bj[j];
        }
    }
}

// ============================================================================
// Kernel B (REWRITTEN): one recurrent step.
// Grid (128 cell-tiles of 32 cells, 2 dirs) = 256 blocks, 128 threads.
// Block tile: 32 batch x 128 local gate cols (= 4 gates x 32 cells).
// Thread tile: 8 batch (4 f32x2 pairs) x 4 cols. 59% FFMA2 density.
// ============================================================================
__global__ void __launch_bounds__(128)
k_gates(const float* __restrict__ Wh, const int* __restrict__ mask, int layer, int s)
{
    const int dir = blockIdx.y;
    const int t   = dir ? (Tsz - 1 - s) : s;
    const int c0  = blockIdx.x * 32;
    const float* __restrict__ W  = Wh + (size_t)(layer*2 + dir) * GATES * HID;
    const float* __restrict__ Pd = g_P + (size_t)dir * 4096 * GATES;
    const float* __restrict__ h  = g_h + dir * Bsz * HID;
    float* __restrict__ c  = g_c  + dir * Bsz * CELLN;
    float* __restrict__ pv = g_pv + dir * Bsz * CELLN;

    __shared__ __align__(16) float hs[32 * 36];   // [k][b], pad 36 (16B-aligned reads)
    __shared__ __align__(16) float ws[32 * 132];  // [k][lc], pad 132; aliased as Gs
    float* Gs = ws;                                // [b][132] gate values after GEMM

    const int tid = threadIdx.x;
    const int tx  = tid & 31;      // local col base tx*4 (0..127)
    const int ty  = tid >> 5;      // batch base ty*8 (0..3)

    // W row index for this thread's fill column
    const int fcol  = tid;                                   // 0..127
    const int fgrow = (fcol >> 5) * CELLN + c0 + (fcol & 31);
    const int flk   = tid & 31, fbq = tid >> 5;

    u64 acc[4][4];   // [bpair][ncol]
#pragma unroll
    for (int p = 0; p < 4; p++)
#pragma unroll
        for (int j = 0; j < 4; j++) acc[p][j] = 0ull;

    for (int kc = 0; kc < HID; kc += 32) {
        // fill hs[k][b]: coalesced LDG over k
#pragma unroll
        for (int i = 0; i < 8; i++) {
            int b = fbq * 8 + i;
            hs[flk * 36 + b] = h[b * HID + kc + flk];
        }
        // fill ws[k][lc]: each thread owns one gate col, 32 consecutive k
        const float* wr = W + (size_t)fgrow * HID + kc;
#pragma unroll
        for (int q = 0; q < 8; q++) {
            float4 w4 = *(const float4*)(wr + q * 4);
            ws[(q * 4 + 0) * 132 + fcol] = w4.x;
            ws[(q * 4 + 1) * 132 + fcol] = w4.y;
            ws[(q * 4 + 2) * 132 + fcol] = w4.z;
            ws[(q * 4 + 3) * 132 + fcol] = w4.w;
        }
        __syncthreads();
#pragma unroll
        for (int kk = 0; kk < 32; kk++) {
            float4 ha = *(const float4*)&hs[kk * 36 + ty * 8];
            float4 hb = *(const float4*)&hs[kk * 36 + ty * 8 + 4];
            u64 h2[4];
            h2[0] = *(const u64*)&ha.x;  h2[1] = *(const u64*)&ha.z;
            h2[2] = *(const u64*)&hb.x;  h2[3] = *(const u64*)&hb.z;
            float4 wv = *(const float4*)&ws[kk * 132 + tx * 4];
            float wa[4] = {wv.x, wv.y, wv.z, wv.w};
#pragma unroll
            for (int j = 0; j < 4; j++) {
                u64 wd = dup2(wa[j]);
#pragma unroll
                for (int p = 0; p < 4; p++) fma2(acc[p][j], h2[p], wd);
            }
        }
        __syncthreads();
    }

    // stage g = acc + P[t] into Gs[b][lc] (ws is free after last sync)
    const int gate  = tx >> 3;
    const int cell0 = (tx & 7) * 4;
#pragma unroll
    for (int p = 0; p < 4; p++) {
        int b = ty * 8 + 2 * p;
        const float* P0 = Pd + ((size_t)(b * Tsz + t) * GATES) + gate * CELLN + c0 + cell0;
        const float* P1 = P0 + (size_t)Tsz * GATES;
        float4 pl0 = *(const float4*)P0;
        float4 pl1 = *(const float4*)P1;
        float2 v0 = unpk(acc[p][0]), v1 = unpk(acc[p][1]);
        float2 v2 = unpk(acc[p][2]), v3 = unpk(acc[p][3]);
        float4 g0 = {v0.x + pl0.x, v1.x + pl0.y, v2.x + pl0.z, v3.x + pl0.w};
        float4 g1 = {v0.y + pl1.x, v1.y + pl1.y, v2.y + pl1.z, v3.y + pl1.w};
        *(float4*)&Gs[b * 132 + tx * 4]       = g0;
        *(float4*)&Gs[(b + 1) * 132 + tx * 4] = g1;
    }
    __syncthreads();

    // elementwise cell update: 1024 (b,cell) pairs / 128 threads
#pragma unroll
    for (int i = 0; i < 8; i++) {
        int e = tid + 128 * i;
        int b = e >> 5, cell = e & 31;
        float ig = sigmoidf_(Gs[b * 132 +  0 + cell]);
        float fg = sigmoidf_(Gs[b * 132 + 32 + cell]);
        float mm =           Gs[b * 132 + 64 + cell];
        float og = sigmoidf_(Gs[b * 132 + 96 + cell]);
        int ci = b * CELLN + c0 + cell;
        float cold = c[ci];
        float cn = ig * tanhf(mm) + fg * cold;
        cn = fminf(3.0f, fmaxf(-3.0f, cn));
        float p2 = og * tanhf(cn);
        c[ci]  = mask[b * Tsz + t] ? cn : cold;
        pv[ci] = p2;
    }
}

// ============================================================================
// Kernel C (REWRITTEN): projection partials.
// Grid (8 n-tiles of 64, 8 K-splits of 512, 2 dirs) = 128 blocks x 256 thr.
// Thread tile: 4 batch (2 pairs) x 2 cols, 8 independent accumulators.
// ============================================================================
__global__ void __launch_bounds__(256)
k_proj(const float* __restrict__ Wp, int layer)
{
    const int dir = blockIdx.z;
    const int n0  = blockIdx.x * 64;
    const int k0  = blockIdx.y * 512;
    const float* __restrict__ W = Wp + (size_t)(layer*2 + dir) * HID * CELLN;
    const float* __restrict__ p = g_pv + dir * Bsz * CELLN;
    float* __restrict__ hp = g_hpart + ((size_t)blockIdx.y * 2 + dir) * Bsz * HID;

    __shared__ __align__(16) float ps[32 * 36];  // [k][b]
    __shared__ __align__(16) float ws[32 * 68];  // [k][n]

    const int tid = threadIdx.x;
    const int tx  = tid & 31;      // n base tx*2 (0..63)
    const int ty  = tid >> 5;      // b base ty*4 (0..7)

    const int flk = tid & 31, fbq = tid >> 5;   // ps fill
    const int fn  = tid & 63, fkq = tid >> 6;   // ws fill

    u64 acc[2][2];
    acc[0][0] = acc[0][1] = acc[1][0] = acc[1][1] = 0ull;

    for (int kc = k0; kc < k0 + 512; kc += 32) {
#pragma unroll
        for (int i = 0; i < 4; i++) {
            int b = fbq * 4 + i;
            ps[flk * 36 + b] = p[b * CELLN + kc + flk];
        }
        const float* wr = W + (size_t)(n0 + fn) * CELLN + kc + fkq * 8;
#pragma unroll
        for (int i = 0; i < 2; i++) {
            float4 w4 = *(const float4*)(wr + i * 4);
            int kb = fkq * 8 + i * 4;
            ws[(kb + 0) * 68 + fn] = w4.x;
            ws[(kb + 1) * 68 + fn] = w4.y;
            ws[(kb + 2) * 68 + fn] = w4.z;
            ws[(kb + 3) * 68 + fn] = w4.w;
        }
        __syncthreads();
#pragma unroll
        for (int kk = 0; kk < 32; kk++) {
            u64 a0 = *(const u64*)&ps[kk * 36 + ty * 4];
            u64 a1 = *(const u64*)&ps[kk * 36 + ty * 4 + 2];
            float2 wv = *(const float2*)&ws[kk * 68 + tx * 2];
            u64 w0 = dup2(wv.x), w1 = dup2(wv.y);
            fma2(acc[0][0], a0, w0); fma2(acc[0][1], a0, w1);
            fma2(acc[1][0], a1, w0); fma2(acc[1][1], a1, w1);
        }
        __syncthreads();
    }

#pragma unroll
    for (int bp = 0; bp < 2; bp++) {
#pragma unroll
        for (int n = 0; n < 2; n++) {
            float2 v = unpk(acc[bp][n]);
            int b = ty * 4 + 2 * bp, col = n0 + tx * 2 + n;
            hp[b * HID + col]       = v.x;
            hp[(b + 1) * HID + col] = v.y;
        }
    }
}

// ============================================================================
// Kernel F: finalize — sum 8 K-split partials, clip +-3, mask, write h + out.
// ============================================================================
__global__ void __launch_bounds__(256)
k_final(const int* __restrict__ mask, int layer, int s, float* __restrict__ out)
{
    int e = blockIdx.x * 256 + threadIdx.x;   // 0..32767 = [dir][b][n]
    int dir = e >> 14;
    int b   = (e >> 9) & 31;
    int n   = e & 511;
    int t = dir ? (Tsz - 1 - s) : s;
    float hv = 0.0f;
#pragma unroll
    for (int ks = 0; ks < 8; ks++) hv += g_hpart[ks * 32768 + e];
    hv = fminf(3.0f, fmaxf(-3.0f, hv));
    int m = mask[b * Tsz + t];
    float hold = g_h[e];
    g_h[e] = m ? hv : hold;
    out[(((size_t)layer * Bsz + b) * Tsz + t) * 1024 + dir * HID + n] = m ? hv : 0.0f;
}

__global__ void __launch_bounds__(256) k_init()
{
    int i = blockIdx.x * 256 + threadIdx.x;   // grid covers 262144
    if (i < 2 * Bsz * HID)   g_h[i] = 0.0f;
    if (i < 2 * Bsz * CELLN) g_c[i] = 0.0f;
}

// residual skip: out[layer1] += out[layer0]
__global__ void __launch_bounds__(256) k_resid(float* __restrict__ out)
{
    size_t i = (size_t)blockIdx.x * 256 + threadIdx.x;  // 4,194,304 total
    out[(size_t)4194304 + i] += out[i];
}

extern "C" void kernel_launch(void* const* d_in, const int* in_sizes, int n_in,
                              void* d_out, int out_size)
{
    const float* x    = (const float*)d_in[0];
    const int*   mask = (const int*)  d_in[1];
    const float* Wx   = (const float*)d_in[2];
    const float* Wh   = (const float*)d_in[3];
    const float* bias = (const float*)d_in[4];
    const float* Wp   = (const float*)d_in[5];
    float* out = (float*)d_out;

    for (int layer = 0; layer < NLAYER; layer++) {
        k_init<<<1024, 256>>>();

        const float* x0; const float* x1; int xs;
        if (layer == 0) { x0 = x;   x1 = x;         xs = IN;   }
        else            { x0 = out; x1 = out + 512; xs = 1024; }

        dim3 gwx(4096 / 128, GATES / 128, 2);
        k_wx<<<gwx, 256>>>(x0, x1, xs, Wx, bias, layer);

        for (int s = 0; s < Tsz; s++) {
            k_gates<<<dim3(128, 2), 128>>>(Wh, mask, layer, s);
            k_proj <<<dim3(8, 8, 2), 256>>>(Wp, layer);
            k_final<<<128, 256>>>(mask, layer, s, out);
        }
    }
    k_resid<<<16384, 256>>>(out);
}

// round 16
// speedup vs baseline: 1.0392x; 1.0347x over previous
#include <cuda_runtime.h>
#include <cstdint>
#include <math.h>

typedef unsigned long long u64;

#define NLAYER 2
#define Bsz    32
#define Tsz    128
#define IN     512
#define HID    512
#define CELLN  4096
#define GATES  16384   /* 4*CELL */

// ---------------- scratch (device globals; no allocation allowed) ----------
__device__ float g_P[(size_t)2*4096*16384]; // [dir][row=b*T+t][16384]
__device__ float g_h[2*Bsz*HID];            // [dir][b][512]
__device__ float g_c[2*Bsz*CELLN];          // [dir][b][4096]
__device__ float g_pv[2*Bsz*CELLN];         // o*tanh(c_new), per step
__device__ float g_hpart[16*2*Bsz*HID];     // [ksplit=16][dir][b][512]

// ---------------- f32x2 helpers (FFMA2 path, sm_103a) ----------------------
__device__ __forceinline__ u64 dup2(float v) {
    u64 r; asm("mov.b64 %0, {%1, %1};" : "=l"(r) : "f"(v)); return r;
}
__device__ __forceinline__ void fma2(u64 &acc, u64 a, u64 b) {
    asm("fma.rn.f32x2 %0, %1, %2, %0;" : "+l"(acc) : "l"(a), "l"(b));
}
__device__ __forceinline__ float2 unpk(u64 v) {
    float2 f; asm("mov.b64 {%0, %1}, %2;" : "=f"(f.x), "=f"(f.y) : "l"(v)); return f;
}
__device__ __forceinline__ float sigmoidf_(float x) { return 1.0f / (1.0f + expf(-x)); }

// ============================================================================
// Kernel A: P = X . Wx^T + b.  (unchanged — near FFMA2 floor, 8192 blocks)
// ============================================================================
__global__ void __launch_bounds__(256)
k_wx(const float* __restrict__ x0, const float* __restrict__ x1, int xstride,
     const float* __restrict__ Wx, const float* __restrict__ bias, int layer)
{
    const int dir = blockIdx.z;
    const float* __restrict__ X  = dir ? x1 : x0;
    const float* __restrict__ W  = Wx   + (size_t)(layer*2 + dir) * GATES * IN;
    const float* __restrict__ bb = bias + (size_t)(layer*2 + dir) * GATES;
    float* __restrict__ Pd = g_P + (size_t)dir * 4096 * GATES;

    __shared__ __align__(16) float As[32][132];
    __shared__ __align__(16) float Bs[32][132];

    const int tid = threadIdx.x;
    const int tx  = tid & 15;
    const int ty  = tid >> 4;
    const int row0 = blockIdx.x * 128;
    const int col0 = blockIdx.y * 128;
    const int lk = tid & 31, lr = tid >> 5;

    u64 acc[4][8];
#pragma unroll
    for (int p = 0; p < 4; p++)
#pragma unroll
        for (int j = 0; j < 8; j++) acc[p][j] = 0ull;

    for (int kc = 0; kc < IN; kc += 32) {
#pragma unroll
        for (int i = 0; i < 16; i++) {
            int r = lr + i * 8;
            As[lk][r] = X[(size_t)(row0 + r) * xstride + kc + lk];
            Bs[lk][r] = W[(size_t)(col0 + r) * IN + kc + lk];
        }
        __syncthreads();
#pragma unroll
        for (int kk = 0; kk < 32; kk++) {
            u64 a2[4];
#pragma unroll
            for (int p = 0; p < 4; p++)
                a2[p] = *(const u64*)&As[kk][ty * 8 + 2 * p];
            float4 w0 = *(const float4*)&Bs[kk][tx * 8];
            float4 w1 = *(const float4*)&Bs[kk][tx * 8 + 4];
            float wv[8] = {w0.x, w0.y, w0.z, w0.w, w1.x, w1.y, w1.z, w1.w};
#pragma unroll
            for (int j = 0; j < 8; j++) {
                u64 bd = dup2(wv[j]);
#pragma unroll
                for (int p = 0; p < 4; p++) fma2(acc[p][j], a2[p], bd);
            }
        }
        __syncthreads();
    }

    float bj[8];
#pragma unroll
    for (int j = 0; j < 8; j++) bj[j] = bb[col0 + tx * 8 + j];
#pragma unroll
    for (int p = 0; p < 4; p++) {
        size_t r0 = (size_t)(row0 + ty * 8 + 2 * p) * GATES + col0 + tx * 8;
#pragma unroll
        for (int j = 0; j < 8; j++) {
            float2 v = unpk(acc[p][j]);
            Pd[r0 + j]         = v.x + bj[j];
            Pd[r0 + GATES + j] = v.y + bj[j];
        }
    }
}

// ============================================================================
// Kernel B (occupancy rework): one recurrent step.
// Grid (256 cell-tiles of 16, 2 dirs) = 512 blocks x 128 thr (~3.5 blocks/SM).
// Block tile: 32 batch x 64 local gate cols (= 4 gates x 16 cells).
// Thread tile: 4 batch (2 f32x2 pairs) x 4 cols.
// ============================================================================
__global__ void __launch_bounds__(128)
k_gates(const float* __restrict__ Wh, const int* __restrict__ mask, int layer, int s)
{
    const int dir = blockIdx.y;
    const int t   = dir ? (Tsz - 1 - s) : s;
    const int c0  = blockIdx.x * 16;
    const float* __restrict__ W  = Wh + (size_t)(layer*2 + dir) * GATES * HID;
    const float* __restrict__ Pd = g_P + (size_t)dir * 4096 * GATES;
    const float* __restrict__ h  = g_h + dir * Bsz * HID;
    float* __restrict__ c  = g_c  + dir * Bsz * CELLN;
    float* __restrict__ pv = g_pv + dir * Bsz * CELLN;

    __shared__ __align__(16) float hs[32 * 36];   // [k][b]
    __shared__ __align__(16) float ws[32 * 68];   // [k][lc]; aliased as Gs after GEMM
    float* Gs = ws;                                // [b][68], cols 0..63

    const int tid = threadIdx.x;
    const int tx  = tid & 15;      // col base tx*4 (0..63)
    const int ty  = tid >> 4;      // batch base ty*4 (0..7)

    const int flk = tid & 31, fbq = tid >> 5;               // hs fill
    const int fcol = tid & 63, fkh = tid >> 6;               // ws fill (2 thr/col)
    const int fgrow = (fcol >> 4) * CELLN + c0 + (fcol & 15);

    u64 acc[2][4];   // [bpair][ncol]
#pragma unroll
    for (int p = 0; p < 2; p++)
#pragma unroll
        for (int j = 0; j < 4; j++) acc[p][j] = 0ull;

    for (int kc = 0; kc < HID; kc += 32) {
#pragma unroll
        for (int i = 0; i < 8; i++) {
            int b = fbq * 8 + i;
            hs[flk * 36 + b] = h[b * HID + kc + flk];
        }
        const float* wr = W + (size_t)fgrow * HID + kc + fkh * 16;
#pragma unroll
        for (int q = 0; q < 4; q++) {
            float4 w4 = *(const float4*)(wr + q * 4);
            int kb = fkh * 16 + q * 4;
            ws[(kb + 0) * 68 + fcol] = w4.x;
            ws[(kb + 1) * 68 + fcol] = w4.y;
            ws[(kb + 2) * 68 + fcol] = w4.z;
            ws[(kb + 3) * 68 + fcol] = w4.w;
        }
        __syncthreads();
#pragma unroll
        for (int kk = 0; kk < 32; kk++) {
            float4 ha = *(const float4*)&hs[kk * 36 + ty * 4];
            u64 h0 = *(const u64*)&ha.x;
            u64 h1 = *(const u64*)&ha.z;
            float4 wv = *(const float4*)&ws[kk * 68 + tx * 4];
            float wa[4] = {wv.x, wv.y, wv.z, wv.w};
#pragma unroll
            for (int j = 0; j < 4; j++) {
                u64 wd = dup2(wa[j]);
                fma2(acc[0][j], h0, wd);
                fma2(acc[1][j], h1, wd);
            }
        }
        __syncthreads();   // also protects ws->Gs alias
    }

    // stage g = acc + P[t] into Gs[b][lc]
    const int gate  = tx >> 2;
    const int cell0 = (tx & 3) * 4;
#pragma unroll
    for (int p = 0; p < 2; p++) {
        int b = ty * 4 + 2 * p;
        const float* P0 = Pd + ((size_t)(b * Tsz + t) * GATES) + gate * CELLN + c0 + cell0;
        const float* P1 = P0 + (size_t)Tsz * GATES;
        float4 pl0 = *(const float4*)P0;
        float4 pl1 = *(const float4*)P1;
        float2 v0 = unpk(acc[p][0]), v1 = unpk(acc[p][1]);
        float2 v2 = unpk(acc[p][2]), v3 = unpk(acc[p][3]);
        float4 g0 = {v0.x + pl0.x, v1.x + pl0.y, v2.x + pl0.z, v3.x + pl0.w};
        float4 g1 = {v0.y + pl1.x, v1.y + pl1.y, v2.y + pl1.z, v3.y + pl1.w};
        *(float4*)&Gs[b * 68 + tx * 4]       = g0;
        *(float4*)&Gs[(b + 1) * 68 + tx * 4] = g1;
    }
    __syncthreads();

    // elementwise cell update: 512 (b,cell) pairs / 128 threads
#pragma unroll
    for (int i = 0; i < 4; i++) {
        int e = tid + 128 * i;
        int b = e >> 4, cell = e & 15;
        float ig = sigmoidf_(Gs[b * 68 +  0 + cell]);
        float fg = sigmoidf_(Gs[b * 68 + 16 + cell]);
        float mm =           Gs[b * 68 + 32 + cell];
        float og = sigmoidf_(Gs[b * 68 + 48 + cell]);
        int ci = b * CELLN + c0 + cell;
        float cold = c[ci];
        float cn = ig * tanhf(mm) + fg * cold;
        cn = fminf(3.0f, fmaxf(-3.0f, cn));
        float p2 = og * tanhf(cn);
        c[ci]  = mask[b * Tsz + t] ? cn : cold;
        pv[ci] = p2;
    }
}

// ============================================================================
// Kernel C (occupancy rework): projection partials.
// Grid (8 n-tiles of 64, 16 K-splits of 256, 2 dirs) = 256 blocks x 128 thr.
// Thread tile: 4 batch (2 pairs) x 4 cols, vectorized LDS.128.
// ============================================================================
__global__ void __launch_bounds__(128)
k_proj(const float* __restrict__ Wp, int layer)
{
    const int dir = blockIdx.z;
    const int n0  = blockIdx.x * 64;
    const int k0  = blockIdx.y * 256;
    const float* __restrict__ W = Wp + (size_t)(layer*2 + dir) * HID * CELLN;
    const float* __restrict__ p = g_pv + dir * Bsz * CELLN;
    float* __restrict__ hp = g_hpart + ((size_t)blockIdx.y * 2 + dir) * Bsz * HID;

    __shared__ __align__(16) float ps[32 * 36];  // [k][b]
    __shared__ __align__(16) float ws[32 * 68];  // [k][n]

    const int tid = threadIdx.x;
    const int tx  = tid & 15;      // n base tx*4 (0..63)
    const int ty  = tid >> 4;      // b base ty*4 (0..7)

    const int flk = tid & 31, fbq = tid >> 5;    // ps fill
    const int fn  = tid & 63, fkh = tid >> 6;    // ws fill (2 thr/col)

    u64 acc[2][4];
#pragma unroll
    for (int q = 0; q < 2; q++)
#pragma unroll
        for (int j = 0; j < 4; j++) acc[q][j] = 0ull;

    for (int kc = k0; kc < k0 + 256; kc += 32) {
#pragma unroll
        for (int i = 0; i < 8; i++) {
            int b = fbq * 8 + i;
            ps[flk * 36 + b] = p[b * CELLN + kc + flk];
        }
        const float* wr = W + (size_t)(n0 + fn) * CELLN + kc + fkh * 16;
#pragma unroll
        for (int q = 0; q < 4; q++) {
            float4 w4 = *(const float4*)(wr + q * 4);
            int kb = fkh * 16 + q * 4;
            ws[(kb + 0) * 68 + fn] = w4.x;
            ws[(kb + 1) * 68 + fn] = w4.y;
            ws[(kb + 2) * 68 + fn] = w4.z;
            ws[(kb + 3) * 68 + fn] = w4.w;
        }
        __syncthreads();
#pragma unroll
        for (int kk = 0; kk < 32; kk++) {
            float4 pa = *(const float4*)&ps[kk * 36 + ty * 4];
            u64 a0 = *(const u64*)&pa.x;
            u64 a1 = *(const u64*)&pa.z;
            float4 wv = *(const float4*)&ws[kk * 68 + tx * 4];
            float wa[4] = {wv.x, wv.y, wv.z, wv.w};
#pragma unroll
            for (int j = 0; j < 4; j++) {
                u64 wd = dup2(wa[j]);
                fma2(acc[0][j], a0, wd);
                fma2(acc[1][j], a1, wd);
            }
        }
        __syncthreads();
    }

#pragma unroll
    for (int q = 0; q < 2; q++) {
        int b = ty * 4 + 2 * q;
#pragma unroll
        for (int j = 0; j < 4; j++) {
            float2 v = unpk(acc[q][j]);
            int col = n0 + tx * 4 + j;
            hp[b * HID + col]       = v.x;
            hp[(b + 1) * HID + col] = v.y;
        }
    }
}

// ============================================================================
// Kernel F: finalize — sum 16 K-split partials, clip +-3, mask, write h + out.
// ============================================================================
__global__ void __launch_bounds__(256)
k_final(const int* __restrict__ mask, int layer, int s, float* __restrict__ out)
{
    int e = blockIdx.x * 256 + threadIdx.x;   // 0..32767 = [dir][b][n]
    int dir = e >> 14;
    int b   = (e >> 9) & 31;
    int n   = e & 511;
    int t = dir ? (Tsz - 1 - s) : s;
    float hv = 0.0f;
#pragma unroll
    for (int ks = 0; ks < 16; ks++) hv += g_hpart[ks * 32768 + e];
    hv = fminf(3.0f, fmaxf(-3.0f, hv));
    int m = mask[b * Tsz + t];
    float hold = g_h[e];
    g_h[e] = m ? hv : hold;
    out[(((size_t)layer * Bsz + b) * Tsz + t) * 1024 + dir * HID + n] = m ? hv : 0.0f;
}

__global__ void __launch_bounds__(256) k_init()
{
    int i = blockIdx.x * 256 + threadIdx.x;   // grid covers 262144
    if (i < 2 * Bsz * HID)   g_h[i] = 0.0f;
    if (i < 2 * Bsz * CELLN) g_c[i] = 0.0f;
}

// residual skip: out[layer1] += out[layer0]
__global__ void __launch_bounds__(256) k_resid(float* __restrict__ out)
{
    size_t i = (size_t)blockIdx.x * 256 + threadIdx.x;  // 4,194,304 total
    out[(size_t)4194304 + i] += out[i];
}

extern "C" void kernel_launch(void* const* d_in, const int* in_sizes, int n_in,
                              void* d_out, int out_size)
{
    const float* x    = (const float*)d_in[0];
    const int*   mask = (const int*)  d_in[1];
    const float* Wx   = (const float*)d_in[2];
    const float* Wh   = (const float*)d_in[3];
    const float* bias = (const float*)d_in[4];
    const float* Wp   = (const float*)d_in[5];
    float* out = (float*)d_out;

    for (int layer = 0; layer < NLAYER; layer++) {
        k_init<<<1024, 256>>>();

        const float* x0; const float* x1; int xs;
        if (layer == 0) { x0 = x;   x1 = x;         xs = IN;   }
        else            { x0 = out; x1 = out + 512; xs = 1024; }

        dim3 gwx(4096 / 128, GATES / 128, 2);
        k_wx<<<gwx, 256>>>(x0, x1, xs, Wx, bias, layer);

        for (int s = 0; s < Tsz; s++) {
            k_gates<<<dim3(256, 2), 128>>>(Wh, mask, layer, s);
            k_proj <<<dim3(8, 16, 2), 128>>>(Wp, layer);
            k_final<<<128, 256>>>(mask, layer, s, out);
        }
    }
    k_resid<<<16384, 256>>>(out);
}

// round 17
// speedup vs baseline: 1.0928x; 1.0516x over previous
#include <cuda_runtime.h>
#include <cstdint>
#include <math.h>

typedef unsigned long long u64;

#define NLAYER 2
#define Bsz    32
#define Tsz    128
#define IN     512
#define HID    512
#define CELLN  4096
#define GATES  16384   /* 4*CELL */

// ---------------- scratch (device globals; no allocation allowed) ----------
__device__ float g_P[(size_t)2*4096*16384]; // [dir][row=b*T+t][16384]
__device__ float g_h[2*Bsz*HID];            // [dir][b][512]
__device__ float g_c[2*Bsz*CELLN];          // [dir][b][4096]
__device__ float g_pv[2*Bsz*CELLN];         // o*tanh(c_new), per step
__device__ float g_hpart[16*2*Bsz*HID];     // [ksplit=16][dir][b][512]

// ---------------- f32x2 helpers (FFMA2 path, sm_103a) ----------------------
__device__ __forceinline__ u64 dup2(float v) {
    u64 r; asm("mov.b64 %0, {%1, %1};" : "=l"(r) : "f"(v)); return r;
}
__device__ __forceinline__ void fma2(u64 &acc, u64 a, u64 b) {
    asm("fma.rn.f32x2 %0, %1, %2, %0;" : "+l"(acc) : "l"(a), "l"(b));
}
__device__ __forceinline__ float2 unpk(u64 v) {
    float2 f; asm("mov.b64 {%0, %1}, %2;" : "=f"(f.x), "=f"(f.y) : "l"(v)); return f;
}
__device__ __forceinline__ float sigmoidf_(float x) { return 1.0f / (1.0f + expf(-x)); }

// ============================================================================
// Kernel A: P = X . Wx^T + b.  (unchanged — deep wave, latency already hidden)
// ============================================================================
__global__ void __launch_bounds__(256)
k_wx(const float* __restrict__ x0, const float* __restrict__ x1, int xstride,
     const float* __restrict__ Wx, const float* __restrict__ bias, int layer)
{
    const int dir = blockIdx.z;
    const float* __restrict__ X  = dir ? x1 : x0;
    const float* __restrict__ W  = Wx   + (size_t)(layer*2 + dir) * GATES * IN;
    const float* __restrict__ bb = bias + (size_t)(layer*2 + dir) * GATES;
    float* __restrict__ Pd = g_P + (size_t)dir * 4096 * GATES;

    __shared__ __align__(16) float As[32][132];
    __shared__ __align__(16) float Bs[32][132];

    const int tid = threadIdx.x;
    const int tx  = tid & 15;
    const int ty  = tid >> 4;
    const int row0 = blockIdx.x * 128;
    const int col0 = blockIdx.y * 128;
    const int lk = tid & 31, lr = tid >> 5;

    u64 acc[4][8];
#pragma unroll
    for (int p = 0; p < 4; p++)
#pragma unroll
        for (int j = 0; j < 8; j++) acc[p][j] = 0ull;

    for (int kc = 0; kc < IN; kc += 32) {
#pragma unroll
        for (int i = 0; i < 16; i++) {
            int r = lr + i * 8;
            As[lk][r] = X[(size_t)(row0 + r) * xstride + kc + lk];
            Bs[lk][r] = W[(size_t)(col0 + r) * IN + kc + lk];
        }
        __syncthreads();
#pragma unroll
        for (int kk = 0; kk < 32; kk++) {
            u64 a2[4];
#pragma unroll
            for (int p = 0; p < 4; p++)
                a2[p] = *(const u64*)&As[kk][ty * 8 + 2 * p];
            float4 w0 = *(const float4*)&Bs[kk][tx * 8];
            float4 w1 = *(const float4*)&Bs[kk][tx * 8 + 4];
            float wv[8] = {w0.x, w0.y, w0.z, w0.w, w1.x, w1.y, w1.z, w1.w};
#pragma unroll
            for (int j = 0; j < 8; j++) {
                u64 bd = dup2(wv[j]);
#pragma unroll
                for (int p = 0; p < 4; p++) fma2(acc[p][j], a2[p], bd);
            }
        }
        __syncthreads();
    }

    float bj[8];
#pragma unroll
    for (int j = 0; j < 8; j++) bj[j] = bb[col0 + tx * 8 + j];
#pragma unroll
    for (int p = 0; p < 4; p++) {
        size_t r0 = (size_t)(row0 + ty * 8 + 2 * p) * GATES + col0 + tx * 8;
#pragma unroll
        for (int j = 0; j < 8; j++) {
            float2 v = unpk(acc[p][j]);
            Pd[r0 + j]         = v.x + bj[j];
            Pd[r0 + GATES + j] = v.y + bj[j];
        }
    }
}

// ============================================================================
// Kernel B (software-pipelined): one recurrent step.
// Grid (128 tiles of 32 cells, 2 dirs) = 256 blocks x 256 thr.
// Block tile: 32 b x 128 lc (4 gates x 32 cells). Thread tile: 4b x 4 cols.
// Double-buffered smem; LDG of chunk k+1 issued before compute of chunk k.
// ============================================================================
__global__ void __launch_bounds__(256)
k_gates(const float* __restrict__ Wh, const int* __restrict__ mask, int layer, int s)
{
    const int dir = blockIdx.y;
    const int t   = dir ? (Tsz - 1 - s) : s;
    const int c0  = blockIdx.x * 32;
    const float* __restrict__ W  = Wh + (size_t)(layer*2 + dir) * GATES * HID;
    const float* __restrict__ Pd = g_P + (size_t)dir * 4096 * GATES;
    const float* __restrict__ h  = g_h + dir * Bsz * HID;
    float* __restrict__ c  = g_c  + dir * Bsz * CELLN;
    float* __restrict__ pv = g_pv + dir * Bsz * CELLN;

    __shared__ __align__(16) float hs[2][32 * 36];   // [buf][k][b]
    __shared__ __align__(16) float ws[2][32 * 132];  // [buf][k][lc]; buf0 aliased as Gs
    float* Gs = ws[0];                                // [b][132]

    const int tid = threadIdx.x;
    const int tx  = tid & 31;      // col base tx*4 (0..127)
    const int ty  = tid >> 5;      // batch base ty*4 (0..7)

    const int flk  = tid & 31, fbq = tid >> 5;   // hs fill: 4 b each
    const int fcol = tid & 127, fkh = tid >> 7;  // ws fill: 2 thr/col, 16 k each
    const int fgrow = (fcol >> 5) * CELLN + c0 + (fcol & 31);
    const float* wbase = W + (size_t)fgrow * HID + fkh * 16;

    u64 acc[2][4];
#pragma unroll
    for (int p = 0; p < 2; p++)
#pragma unroll
        for (int j = 0; j < 4; j++) acc[p][j] = 0ull;

    float  hreg[4];
    float4 wreg[4];

    // prologue: load chunk 0
#pragma unroll
    for (int i = 0; i < 4; i++) hreg[i] = h[(fbq * 4 + i) * HID + flk];
#pragma unroll
    for (int q = 0; q < 4; q++) wreg[q] = *(const float4*)(wbase + q * 4);
    {
#pragma unroll
        for (int i = 0; i < 4; i++) hs[0][flk * 36 + fbq * 4 + i] = hreg[i];
#pragma unroll
        for (int q = 0; q < 4; q++) {
            int kb = fkh * 16 + q * 4;
            ws[0][(kb + 0) * 132 + fcol] = wreg[q].x;
            ws[0][(kb + 1) * 132 + fcol] = wreg[q].y;
            ws[0][(kb + 2) * 132 + fcol] = wreg[q].z;
            ws[0][(kb + 3) * 132 + fcol] = wreg[q].w;
        }
    }
    __syncthreads();

#pragma unroll 1
    for (int chunk = 0; chunk < 16; chunk++) {
        const int cur = chunk & 1;
        if (chunk < 15) {
            const int kc = (chunk + 1) * 32;
#pragma unroll
            for (int i = 0; i < 4; i++) hreg[i] = h[(fbq * 4 + i) * HID + kc + flk];
            const float* wr = wbase + kc;
#pragma unroll
            for (int q = 0; q < 4; q++) wreg[q] = *(const float4*)(wr + q * 4);
        }
        const float* hb = &hs[cur][0];
        const float* wb = &ws[cur][0];
#pragma unroll
        for (int kk = 0; kk < 32; kk++) {
            float4 ha = *(const float4*)&hb[kk * 36 + ty * 4];
            u64 h0 = *(const u64*)&ha.x;
            u64 h1 = *(const u64*)&ha.z;
            float4 wv = *(const float4*)&wb[kk * 132 + tx * 4];
            float wa[4] = {wv.x, wv.y, wv.z, wv.w};
#pragma unroll
            for (int j = 0; j < 4; j++) {
                u64 wd = dup2(wa[j]);
                fma2(acc[0][j], h0, wd);
                fma2(acc[1][j], h1, wd);
            }
        }
        if (chunk < 15) {
            const int nxt = cur ^ 1;
#pragma unroll
            for (int i = 0; i < 4; i++) hs[nxt][flk * 36 + fbq * 4 + i] = hreg[i];
#pragma unroll
            for (int q = 0; q < 4; q++) {
                int kb = fkh * 16 + q * 4;
                ws[nxt][(kb + 0) * 132 + fcol] = wreg[q].x;
                ws[nxt][(kb + 1) * 132 + fcol] = wreg[q].y;
                ws[nxt][(kb + 2) * 132 + fcol] = wreg[q].z;
                ws[nxt][(kb + 3) * 132 + fcol] = wreg[q].w;
            }
            __syncthreads();
        }
    }
    // NOTE: last chunk (15) computed from buf1; Gs aliases buf0, whose last
    // readers finished before the chunk-14 barrier -> safe to write now.

    // stage g = acc + P[t] into Gs[b][lc]
    const int gate  = tx >> 3;
    const int cell0 = (tx & 7) * 4;
#pragma unroll
    for (int p = 0; p < 2; p++) {
        int b = ty * 4 + 2 * p;
        const float* P0 = Pd + ((size_t)(b * Tsz + t) * GATES) + gate * CELLN + c0 + cell0;
        const float* P1 = P0 + (size_t)Tsz * GATES;
        float4 pl0 = *(const float4*)P0;
        float4 pl1 = *(const float4*)P1;
        float2 v0 = unpk(acc[p][0]), v1 = unpk(acc[p][1]);
        float2 v2 = unpk(acc[p][2]), v3 = unpk(acc[p][3]);
        float4 g0 = {v0.x + pl0.x, v1.x + pl0.y, v2.x + pl0.z, v3.x + pl0.w};
        float4 g1 = {v0.y + pl1.x, v1.y + pl1.y, v2.y + pl1.z, v3.y + pl1.w};
        *(float4*)&Gs[b * 132 + tx * 4]       = g0;
        *(float4*)&Gs[(b + 1) * 132 + tx * 4] = g1;
    }
    __syncthreads();

    // elementwise cell update: 1024 (b,cell) pairs / 256 threads
#pragma unroll
    for (int i = 0; i < 4; i++) {
        int e = tid + 256 * i;
        int b = e >> 5, cell = e & 31;
        float ig = sigmoidf_(Gs[b * 132 +  0 + cell]);
        float fg = sigmoidf_(Gs[b * 132 + 32 + cell]);
        float mm =           Gs[b * 132 + 64 + cell];
        float og = sigmoidf_(Gs[b * 132 + 96 + cell]);
        int ci = b * CELLN + c0 + cell;
        float cold = c[ci];
        float cn = ig * tanhf(mm) + fg * cold;
        cn = fminf(3.0f, fmaxf(-3.0f, cn));
        float p2 = og * tanhf(cn);
        c[ci]  = mask[b * Tsz + t] ? cn : cold;
        pv[ci] = p2;
    }
}

// ============================================================================
// Kernel C (software-pipelined): projection partials.
// Grid (8 n-tiles of 64, 16 K-splits of 256, 2 dirs) = 256 blocks x 256 thr.
// Block tile 32 b x 64 n; thread tile 4b x 2n. Double-buffered smem.
// ============================================================================
__global__ void __launch_bounds__(256)
k_proj(const float* __restrict__ Wp, int layer)
{
    const int dir = blockIdx.z;
    const int n0  = blockIdx.x * 64;
    const int k0  = blockIdx.y * 256;
    const float* __restrict__ W = Wp + (size_t)(layer*2 + dir) * HID * CELLN;
    const float* __restrict__ p = g_pv + dir * Bsz * CELLN;
    float* __restrict__ hp = g_hpart + ((size_t)blockIdx.y * 2 + dir) * Bsz * HID;

    __shared__ __align__(16) float ps[2][32 * 36];  // [buf][k][b]
    __shared__ __align__(16) float ws[2][32 * 68];  // [buf][k][n]

    const int tid = threadIdx.x;
    const int tx  = tid & 31;      // n base tx*2 (0..63)
    const int ty  = tid >> 5;      // b base ty*4 (0..7)

    const int flk = tid & 31, fbq = tid >> 5;    // ps fill: 4 b each
    const int fn  = tid & 63, fkq = tid >> 6;    // ws fill: 4 thr/col, 8 k each
    const float* wbase = W + (size_t)(n0 + fn) * CELLN + k0 + fkq * 8;

    u64 acc[2][2];
    acc[0][0] = acc[0][1] = acc[1][0] = acc[1][1] = 0ull;

    float  preg[4];
    float4 wreg[2];

#pragma unroll
    for (int i = 0; i < 4; i++) preg[i] = p[(fbq * 4 + i) * CELLN + k0 + flk];
    wreg[0] = *(const float4*)(wbase);
    wreg[1] = *(const float4*)(wbase + 4);
    {
#pragma unroll
        for (int i = 0; i < 4; i++) ps[0][flk * 36 + fbq * 4 + i] = preg[i];
#pragma unroll
        for (int q = 0; q < 2; q++) {
            int kb = fkq * 8 + q * 4;
            ws[0][(kb + 0) * 68 + fn] = wreg[q].x;
            ws[0][(kb + 1) * 68 + fn] = wreg[q].y;
            ws[0][(kb + 2) * 68 + fn] = wreg[q].z;
            ws[0][(kb + 3) * 68 + fn] = wreg[q].w;
        }
    }
    __syncthreads();

#pragma unroll 1
    for (int chunk = 0; chunk < 8; chunk++) {
        const int cur = chunk & 1;
        if (chunk < 7) {
            const int kc = k0 + (chunk + 1) * 32;
#pragma unroll
            for (int i = 0; i < 4; i++) preg[i] = p[(fbq * 4 + i) * CELLN + kc + flk];
            const float* wr = wbase + (chunk + 1) * 32;
            wreg[0] = *(const float4*)(wr);
            wreg[1] = *(const float4*)(wr + 4);
        }
        const float* pb = &ps[cur][0];
        const float* wb = &ws[cur][0];
#pragma unroll
        for (int kk = 0; kk < 32; kk++) {
            float4 pa = *(const float4*)&pb[kk * 36 + ty * 4];
            u64 a0 = *(const u64*)&pa.x;
            u64 a1 = *(const u64*)&pa.z;
            float2 wv = *(const float2*)&wb[kk * 68 + tx * 2];
            u64 w0 = dup2(wv.x), w1 = dup2(wv.y);
            fma2(acc[0][0], a0, w0); fma2(acc[0][1], a0, w1);
            fma2(acc[1][0], a1, w0); fma2(acc[1][1], a1, w1);
        }
        if (chunk < 7) {
            const int nxt = cur ^ 1;
#pragma unroll
            for (int i = 0; i < 4; i++) ps[nxt][flk * 36 + fbq * 4 + i] = preg[i];
#pragma unroll
            for (int q = 0; q < 2; q++) {
                int kb = fkq * 8 + q * 4;
                ws[nxt][(kb + 0) * 68 + fn] = wreg[q].x;
                ws[nxt][(kb + 1) * 68 + fn] = wreg[q].y;
                ws[nxt][(kb + 2) * 68 + fn] = wreg[q].z;
                ws[nxt][(kb + 3) * 68 + fn] = wreg[q].w;
            }
            __syncthreads();
        }
    }

#pragma unroll
    for (int q = 0; q < 2; q++) {
        int b = ty * 4 + 2 * q;
#pragma unroll
        for (int j = 0; j < 2; j++) {
            float2 v = unpk(acc[q][j]);
            int col = n0 + tx * 2 + j;
            hp[b * HID + col]       = v.x;
            hp[(b + 1) * HID + col] = v.y;
        }
    }
}

// ============================================================================
// Kernel F: finalize — sum 16 K-split partials, clip +-3, mask, write h + out.
// ============================================================================
__global__ void __launch_bounds__(256)
k_final(const int* __restrict__ mask, int layer, int s, float* __restrict__ out)
{
    int e = blockIdx.x * 256 + threadIdx.x;   // 0..32767 = [dir][b][n]
    int dir = e >> 14;
    int b   = (e >> 9) & 31;
    int n   = e & 511;
    int t = dir ? (Tsz - 1 - s) : s;
    float hv = 0.0f;
#pragma unroll
    for (int ks = 0; ks < 16; ks++) hv += g_hpart[ks * 32768 + e];
    hv = fminf(3.0f, fmaxf(-3.0f, hv));
    int m = mask[b * Tsz + t];
    float hold = g_h[e];
    g_h[e] = m ? hv : hold;
    out[(((size_t)layer * Bsz + b) * Tsz + t) * 1024 + dir * HID + n] = m ? hv : 0.0f;
}

__global__ void __launch_bounds__(256) k_init()
{
    int i = blockIdx.x * 256 + threadIdx.x;   // grid covers 262144
    if (i < 2 * Bsz * HID)   g_h[i] = 0.0f;
    if (i < 2 * Bsz * CELLN) g_c[i] = 0.0f;
}

// residual skip: out[layer1] += out[layer0]
__global__ void __launch_bounds__(256) k_resid(float* __restrict__ out)
{
    size_t i = (size_t)blockIdx.x * 256 + threadIdx.x;  // 4,194,304 total
    out[(size_t)4194304 + i] += out[i];
}

extern "C" void kernel_launch(void* const* d_in, const int* in_sizes, int n_in,
                              void* d_out, int out_size)
{
    const float* x    = (const float*)d_in[0];
    const int*   mask = (const int*)  d_in[1];
    const float* Wx   = (const float*)d_in[2];
    const float* Wh   = (const float*)d_in[3];
    const float* bias = (const float*)d_in[4];
    const float* Wp   = (const float*)d_in[5];
    float* out = (float*)d_out;

    for (int layer = 0; layer < NLAYER; layer++) {
        k_init<<<1024, 256>>>();

        const float* x0; const float* x1; int xs;
        if (layer == 0) { x0 = x;   x1 = x;         xs = IN;   }
        else            { x0 = out; x1 = out + 512; xs = 1024; }

        dim3 gwx(4096 / 128, GATES / 128, 2);
        k_wx<<<gwx, 256>>>(x0, x1, xs, Wx, bias, layer);

        for (int s = 0; s < Tsz; s++) {
            k_gates<<<dim3(128, 2), 256>>>(Wh, mask, layer, s);
            k_proj <<<dim3(8, 16, 2), 256>>>(Wp, layer);
            k_final<<<128, 256>>>(mask, layer, s, out);
        }
    }
    k_resid<<<16384, 256>>>(out);
}